// round 13
// baseline (speedup 1.0000x reference)
#include <cuda_runtime.h>
#include <math.h>

#define NEG_INF (-1e10f)
#define BATCH 4
#define NN 1024
#define DD 32
#define WPR 32   // u32 words per bitset row
#define FULL 0xFFFFFFFFu

#define PACK_BLOCKS (BATCH * NN / 8)        // 512, warp per row
#define GMAX_BLOCKS (BATCH * 32 / 8)        // 16,  warp per (b,group)

// 512KB bitset scratch + 16KB group-max scratch (device globals: allowed)
__device__ unsigned g_bits[BATCH * NN * WPR];
__device__ float    g_gm[BATCH * 32 * DD];   // [b][group][d]

// ---------------------------------------------------------------------------
// Fused: pack edges -> bitset rows (blocks [0,512)) + group maxes (blocks
// [512,528)). Pack: one warp per row, uint4 loads front-batched (MLP=8),
// shfl-OR reduce. launch_bounds(256,2): 128-reg budget for the load batch.
// ---------------------------------------------------------------------------
__global__ __launch_bounds__(256, 2)
void pack_gmax_kernel(const int* __restrict__ edges,
                      const float* __restrict__ feat) {
    const int lane = threadIdx.x & 31;
    const int warp = threadIdx.x >> 5;

    if (blockIdx.x < PACK_BLOCKS) {
        const int rowId = blockIdx.x * 8 + warp;            // 0..4095
        const uint4* row = (const uint4*)(edges + (size_t)rowId * NN);
        // Front-batch all 8 uint4 loads.
        uint4 v[8];
        #pragma unroll
        for (int i = 0; i < 8; ++i) v[i] = row[i * 32 + lane];

        unsigned myword = 0u;
        #pragma unroll
        for (int i = 0; i < 8; ++i) {
            unsigned nib = (unsigned)(v[i].x != 0)
                         | ((unsigned)(v[i].y != 0) << 1)
                         | ((unsigned)(v[i].z != 0) << 2)
                         | ((unsigned)(v[i].w != 0) << 3);
            unsigned val = nib << ((lane & 7) * 4);
            // OR-butterfly within each 8-lane group -> word (i*4 + lane>>3)
            val |= __shfl_xor_sync(FULL, val, 1);
            val |= __shfl_xor_sync(FULL, val, 2);
            val |= __shfl_xor_sync(FULL, val, 4);
            // lane 4i+g grabs word g of this iteration (held by lane g*8)
            unsigned w = __shfl_sync(FULL, val, (lane & 3) << 3);
            if ((lane >> 2) == i) myword = w;
        }
        g_bits[rowId * WPR + lane] = myword;                // coalesced
    } else {
        // group maxes: warp per (b,group); idx = b*32+g in [0,128)
        const int idx = (blockIdx.x - PACK_BLOCKS) * 8 + warp;
        const float* f = feat + (size_t)idx * 32 * DD + lane;
        float m0 = f[0], m1 = f[DD], m2 = f[2 * DD], m3 = f[3 * DD];
        #pragma unroll
        for (int j = 4; j < 32; j += 4) {
            m0 = fmaxf(m0, f[j * DD]);
            m1 = fmaxf(m1, f[(j + 1) * DD]);
            m2 = fmaxf(m2, f[(j + 2) * DD]);
            m3 = fmaxf(m3, f[(j + 3) * DD]);
        }
        g_gm[idx * DD + lane] = fmaxf(fmaxf(m0, m1), fmaxf(m2, m3));
    }
}

// ---------------------------------------------------------------------------
// Pool: round-0 neighbor rows (rows 0..31) and the group-max table are the
// SAME for every block of a batch -> stage both into smem cooperatively
// (2 x 4KB, one L2 epoch, overlapped with the per-warp rw load). Round 0 and
// the saturated-max chain then run entirely from LDS: ONE L2 epoch per warp.
// ~1.5% of rows not saturated after round 0 fall through to exact global
// rounds (w>=1, masked unconditional loads) + exact general pooling.
// launch_bounds(256,4), regs<64, smem 8KB -> all 512 blocks in ONE wave.
// ---------------------------------------------------------------------------
__global__ __launch_bounds__(256, 4)
void pool_kernel(const float* __restrict__ feat, float* __restrict__ out) {
    __shared__ unsigned sbits[32 * WPR];   // 4KB: bitset rows 0..31
    __shared__ float    sgm[32 * DD];      // 4KB: group maxes

    const int b    = blockIdx.y;
    const int tid  = threadIdx.x;
    const int lane = tid & 31;
    const int warp = tid >> 5;
    const int i    = blockIdx.x * 8 + warp;        // output row

    const unsigned* __restrict__ bb = g_bits + (size_t)b * NN * WPR;
    const float*    __restrict__ gm = g_gm + b * 32 * DD;
    const float*    __restrict__ fb = feat + (size_t)b * NN * DD;

    // All three loads below are independent -> one L2 epoch.
    const unsigned rw = bb[i * WPR + lane];                 // row i of E
    ((uint4*)sbits)[tid]  = ((const uint4*)bb)[tid];        // rows 0..31
    ((float4*)sgm)[tid]   = ((const float4*)gm)[tid];       // group maxes
    __syncthreads();

    // --- round 0 (word 0) from smem: OR rows 0..31 masked by bits of m ---
    unsigned acc = 0u;
    bool sat;
    {
        const unsigned m = __shfl_sync(FULL, rw, 0);        // warp-uniform
        unsigned v0 = 0u, v1 = 0u, v2 = 0u, v3 = 0u;
        unsigned v4 = 0u, v5 = 0u, v6 = 0u, v7 = 0u;
        #pragma unroll
        for (int t = 0; t < 32; t += 8) {
            v0 |= sbits[((t    ) << 5) + lane] & (0u - ((m >> (t    )) & 1u));
            v1 |= sbits[((t + 1) << 5) + lane] & (0u - ((m >> (t + 1)) & 1u));
            v2 |= sbits[((t + 2) << 5) + lane] & (0u - ((m >> (t + 2)) & 1u));
            v3 |= sbits[((t + 3) << 5) + lane] & (0u - ((m >> (t + 3)) & 1u));
            v4 |= sbits[((t + 4) << 5) + lane] & (0u - ((m >> (t + 4)) & 1u));
            v5 |= sbits[((t + 5) << 5) + lane] & (0u - ((m >> (t + 5)) & 1u));
            v6 |= sbits[((t + 6) << 5) + lane] & (0u - ((m >> (t + 6)) & 1u));
            v7 |= sbits[((t + 7) << 5) + lane] & (0u - ((m >> (t + 7)) & 1u));
        }
        acc = ((v0 | v1) | (v2 | v3)) | ((v4 | v5) | (v6 | v7));
        sat = __all_sync(FULL, acc == FULL);
    }

    // --- rare rounds w>=1 from global (exact) ---
    #pragma unroll 1
    for (int w = 1; w < 32 && !sat; ++w) {
        const unsigned m = __shfl_sync(FULL, rw, w);
        if (!m) continue;
        const unsigned* __restrict__ gp = bb + ((size_t)w << 10) + lane;
        unsigned v0 = 0u, v1 = 0u, v2 = 0u, v3 = 0u;
        unsigned v4 = 0u, v5 = 0u, v6 = 0u, v7 = 0u;
        #pragma unroll
        for (int t = 0; t < 32; t += 8) {
            v0 |= gp[(t    ) << 5] & (0u - ((m >> (t    )) & 1u));
            v1 |= gp[(t + 1) << 5] & (0u - ((m >> (t + 1)) & 1u));
            v2 |= gp[(t + 2) << 5] & (0u - ((m >> (t + 2)) & 1u));
            v3 |= gp[(t + 3) << 5] & (0u - ((m >> (t + 3)) & 1u));
            v4 |= gp[(t + 4) << 5] & (0u - ((m >> (t + 4)) & 1u));
            v5 |= gp[(t + 5) << 5] & (0u - ((m >> (t + 5)) & 1u));
            v6 |= gp[(t + 6) << 5] & (0u - ((m >> (t + 6)) & 1u));
            v7 |= gp[(t + 7) << 5] & (0u - ((m >> (t + 7)) & 1u));
        }
        acc |= ((v0 | v1) | (v2 | v3)) | ((v4 | v5) | (v6 | v7));
        sat = __all_sync(FULL, acc == FULL);
    }

    float best;
    if (sat) {
        // Everything visible: max over all group maxes, from smem.
        best = sgm[lane];
        #pragma unroll
        for (int g = 1; g < 32; ++g) best = fmaxf(best, sgm[(g << 5) + lane]);
    } else {
        best = -INFINITY;
        #pragma unroll 1
        for (int g = 0; g < 32; ++g) {
            const unsigned mg = __shfl_sync(FULL, acc, g);   // uniform
            const float gmv = sgm[(g << 5) + lane];
            float v;
            if (mg == FULL) {
                v = gmv;                        // whole group visible
            } else if (mg == 0u) {
                v = gmv + NEG_INF;              // whole group masked (exact)
            } else {
                v = -INFINITY;                  // mixed group: per-element
                for (int jj = 0; jj < 32; ++jj) {
                    float fv = fb[(size_t)((g << 5) + jj) * DD + lane];
                    v = fmaxf(v, fv + (((mg >> jj) & 1u) ? 0.0f : NEG_INF));
                }
            }
            best = fmaxf(best, v);
        }
    }
    out[((size_t)b * NN + i) * DD + lane] = best;   // coalesced 128B/warp
}

// ---------------------------------------------------------------------------
extern "C" void kernel_launch(void* const* d_in, const int* in_sizes, int n_in,
                              void* d_out, int out_size) {
    const float* feat;
    const int*   edges;
    if (in_sizes[0] == BATCH * NN * DD) {
        feat  = (const float*)d_in[0];
        edges = (const int*)d_in[1];
    } else {
        feat  = (const float*)d_in[1];
        edges = (const int*)d_in[0];
    }

    pack_gmax_kernel<<<PACK_BLOCKS + GMAX_BLOCKS, 256>>>(edges, feat);
    pool_kernel<<<dim3(NN / 8, BATCH), 256>>>(feat, (float*)d_out);

    (void)n_in; (void)out_size;
}

// round 14
// speedup vs baseline: 1.0179x; 1.0179x over previous
#include <cuda_runtime.h>
#include <math.h>

#define NEG_INF (-1e10f)
#define BATCH 4
#define NN 1024
#define DD 32
#define WPR 32   // u32 words per bitset row
#define FULL 0xFFFFFFFFu

#define PACK_BLOCKS (BATCH * NN / 8)        // 512, warp per row
#define GMAX_BLOCKS (BATCH * 32 / 8)        // 16,  warp per (b,group)

// 512KB bitset scratch + 16KB group-max scratch (device globals: allowed)
__device__ unsigned g_bits[BATCH * NN * WPR];
__device__ float    g_gm[BATCH * 32 * DD];   // [b][group][d]

// ---------------------------------------------------------------------------
// Fused: pack edges -> bitset rows (blocks [0,512)) + group maxes (blocks
// [512,528)). Pack: one warp per row, 2 batches of 4 front-batched uint4
// loads (fits the 64-reg cap of launch_bounds(256,4) -> ONE wave for all
// 528 blocks), shfl-OR reduce.
// ---------------------------------------------------------------------------
__global__ __launch_bounds__(256, 4)
void pack_gmax_kernel(const int* __restrict__ edges,
                      const float* __restrict__ feat) {
    const int lane = threadIdx.x & 31;
    const int warp = threadIdx.x >> 5;

    if (blockIdx.x < PACK_BLOCKS) {
        const int rowId = blockIdx.x * 8 + warp;            // 0..4095
        const uint4* row = (const uint4*)(edges + (size_t)rowId * NN);
        unsigned myword = 0u;
        #pragma unroll
        for (int h = 0; h < 2; ++h) {
            uint4 v[4];
            #pragma unroll
            for (int j = 0; j < 4; ++j) v[j] = row[(h * 4 + j) * 32 + lane];
            #pragma unroll
            for (int j = 0; j < 4; ++j) {
                const int i = h * 4 + j;
                unsigned nib = (unsigned)(v[j].x != 0)
                             | ((unsigned)(v[j].y != 0) << 1)
                             | ((unsigned)(v[j].z != 0) << 2)
                             | ((unsigned)(v[j].w != 0) << 3);
                unsigned val = nib << ((lane & 7) * 4);
                // OR-butterfly within each 8-lane group
                val |= __shfl_xor_sync(FULL, val, 1);
                val |= __shfl_xor_sync(FULL, val, 2);
                val |= __shfl_xor_sync(FULL, val, 4);
                // lane 4i+g grabs word g (held by lane g*8)
                unsigned w = __shfl_sync(FULL, val, (lane & 3) << 3);
                if ((lane >> 2) == i) myword = w;
            }
        }
        g_bits[rowId * WPR + lane] = myword;                // coalesced
    } else {
        // group maxes: warp per (b,group); idx = b*32+g in [0,128)
        const int idx = (blockIdx.x - PACK_BLOCKS) * 8 + warp;
        const float* f = feat + (size_t)idx * 32 * DD + lane;
        float m0 = f[0], m1 = f[DD], m2 = f[2 * DD], m3 = f[3 * DD];
        #pragma unroll
        for (int j = 4; j < 32; j += 4) {
            m0 = fmaxf(m0, f[j * DD]);
            m1 = fmaxf(m1, f[(j + 1) * DD]);
            m2 = fmaxf(m2, f[(j + 2) * DD]);
            m3 = fmaxf(m3, f[(j + 3) * DD]);
        }
        g_gm[idx * DD + lane] = fmaxf(fmaxf(m0, m1), fmaxf(m2, m3));
    }
}

// ---------------------------------------------------------------------------
// Pool, instruction-minimized:
//  - stage bitset rows 0..31 (4KB) cooperatively; warp 0 additionally
//    computes the batch max over group maxes ONCE into sbmax[32];
//  - round 0 from LDS with 4-instr/element masking (shf,shf,lds,lop3);
//  - saturated rows (~98.5%): 1 LDS + STG. Fallback paths exact, from L2.
// launch_bounds(256,4): 512 blocks -> ONE wave.
// ---------------------------------------------------------------------------
__global__ __launch_bounds__(256, 4)
void pool_kernel(const float* __restrict__ feat, float* __restrict__ out) {
    __shared__ unsigned sbits[32 * WPR];   // 4KB: bitset rows 0..31
    __shared__ float    sbmax[32];         // batch max over group maxes

    const int b    = blockIdx.y;
    const int tid  = threadIdx.x;
    const int lane = tid & 31;
    const int warp = tid >> 5;
    const int i    = blockIdx.x * 8 + warp;        // output row

    const unsigned* __restrict__ bb = g_bits + (size_t)b * NN * WPR;
    const float*    __restrict__ gm = g_gm + b * 32 * DD;
    const float*    __restrict__ fb = feat + (size_t)b * NN * DD;

    // One L2 epoch: rw + rows 0..31 stage + (warp0) gm reduction loads.
    const unsigned rw = bb[i * WPR + lane];                 // row i of E
    ((uint4*)sbits)[tid] = ((const uint4*)bb)[tid];         // rows 0..31
    if (warp == 0) {
        float m0 = gm[lane],            m1 = gm[32 + lane];
        float m2 = gm[64 + lane],       m3 = gm[96 + lane];
        #pragma unroll
        for (int g = 4; g < 32; g += 4) {
            m0 = fmaxf(m0, gm[(g    ) * 32 + lane]);
            m1 = fmaxf(m1, gm[(g + 1) * 32 + lane]);
            m2 = fmaxf(m2, gm[(g + 2) * 32 + lane]);
            m3 = fmaxf(m3, gm[(g + 3) * 32 + lane]);
        }
        sbmax[lane] = fmaxf(fmaxf(m0, m1), fmaxf(m2, m3));
    }
    __syncthreads();

    // --- round 0 (word 0) from smem ---
    unsigned acc;
    bool sat;
    {
        const unsigned m = __shfl_sync(FULL, rw, 0);        // warp-uniform
        unsigned v0 = 0u, v1 = 0u, v2 = 0u, v3 = 0u;
        #pragma unroll
        for (int t = 0; t < 32; t += 4) {
            v0 |= sbits[((t    ) << 5) + lane] & (unsigned)((int)(m << (31 - t    )) >> 31);
            v1 |= sbits[((t + 1) << 5) + lane] & (unsigned)((int)(m << (31 - t - 1)) >> 31);
            v2 |= sbits[((t + 2) << 5) + lane] & (unsigned)((int)(m << (31 - t - 2)) >> 31);
            v3 |= sbits[((t + 3) << 5) + lane] & (unsigned)((int)(m << (31 - t - 3)) >> 31);
        }
        acc = (v0 | v1) | (v2 | v3);
        sat = __all_sync(FULL, acc == FULL);
    }

    if (sat) {
        out[((size_t)b * NN + i) * DD + lane] = sbmax[lane];
        return;
    }

    // --- rare rounds w>=1 from global (exact) ---
    #pragma unroll 1
    for (int w = 1; w < 32 && !sat; ++w) {
        const unsigned m = __shfl_sync(FULL, rw, w);
        if (!m) continue;
        const unsigned* __restrict__ gp = bb + ((size_t)w << 10) + lane;
        unsigned v0 = 0u, v1 = 0u, v2 = 0u, v3 = 0u;
        #pragma unroll
        for (int t = 0; t < 32; t += 4) {
            v0 |= gp[(t    ) << 5] & (unsigned)((int)(m << (31 - t    )) >> 31);
            v1 |= gp[(t + 1) << 5] & (unsigned)((int)(m << (31 - t - 1)) >> 31);
            v2 |= gp[(t + 2) << 5] & (unsigned)((int)(m << (31 - t - 2)) >> 31);
            v3 |= gp[(t + 3) << 5] & (unsigned)((int)(m << (31 - t - 3)) >> 31);
        }
        acc |= (v0 | v1) | (v2 | v3);
        sat = __all_sync(FULL, acc == FULL);
    }

    float best;
    if (sat) {
        best = sbmax[lane];
    } else {
        best = -INFINITY;
        #pragma unroll 1
        for (int g = 0; g < 32; ++g) {
            const unsigned mg = __shfl_sync(FULL, acc, g);   // uniform
            const float gmv = gm[(g << 5) + lane];           // L2
            float v;
            if (mg == FULL) {
                v = gmv;                        // whole group visible
            } else if (mg == 0u) {
                v = gmv + NEG_INF;              // whole group masked (exact)
            } else {
                v = -INFINITY;                  // mixed group: per-element
                for (int jj = 0; jj < 32; ++jj) {
                    float fv = fb[(size_t)((g << 5) + jj) * DD + lane];
                    v = fmaxf(v, fv + (((mg >> jj) & 1u) ? 0.0f : NEG_INF));
                }
            }
            best = fmaxf(best, v);
        }
    }
    out[((size_t)b * NN + i) * DD + lane] = best;   // coalesced 128B/warp
}

// ---------------------------------------------------------------------------
extern "C" void kernel_launch(void* const* d_in, const int* in_sizes, int n_in,
                              void* d_out, int out_size) {
    const float* feat;
    const int*   edges;
    if (in_sizes[0] == BATCH * NN * DD) {
        feat  = (const float*)d_in[0];
        edges = (const int*)d_in[1];
    } else {
        feat  = (const float*)d_in[1];
        edges = (const int*)d_in[0];
    }

    pack_gmax_kernel<<<PACK_BLOCKS + GMAX_BLOCKS, 256>>>(edges, feat);
    pool_kernel<<<dim3(NN / 8, BATCH), 256>>>(feat, (float*)d_out);

    (void)n_in; (void)out_size;
}

// round 15
// speedup vs baseline: 1.0209x; 1.0030x over previous
#include <cuda_runtime.h>
#include <math.h>

#define NEG_INF (-1e10f)
#define BATCH 4
#define NN 1024
#define DD 32
#define WPR 32   // u32 words per bitset row
#define FULL 0xFFFFFFFFu
#define NB   (BATCH * NN / 8)   // 512 blocks, 8 rows each

// 512KB bitset scratch + 16KB group-max scratch (device globals: allowed)
__device__ unsigned g_bits[BATCH * NN * WPR];
__device__ float    g_gm[BATCH * 32 * DD];   // [b][group][d]
__device__ unsigned g_arrive;                 // monotonic grid-barrier counter

// ---------------------------------------------------------------------------
// ONE persistent kernel, 512 blocks, all co-resident (4 blocks/SM x 148 SM
// = 592 slots >= 512) -> device-wide barrier is deadlock-free.
// Phase 1: pack edges->bitsets (8 rows/block) + group maxes (blocks 0..15).
// Barrier: CG-style monotonic-counter barrier (epoch = t/NB), graph-safe.
// Phase 2: E2 row build from smem-staged rows 0..31 + saturated fast path;
//          exact global fallbacks for non-saturated rows.
// ---------------------------------------------------------------------------
__global__ __launch_bounds__(256, 4)
void fused_kernel(const int* __restrict__ edges,
                  const float* __restrict__ feat,
                  float* __restrict__ out) {
    __shared__ unsigned sbits[32 * WPR];   // 4KB: bitset rows 0..31 (phase 2)
    __shared__ float    sbmax[32];         // batch max over group maxes

    const int tid  = threadIdx.x;
    const int lane = tid & 31;
    const int warp = tid >> 5;

    // ===================== Phase 1: pack + gmax =====================
    {
        const int rowId = blockIdx.x * 8 + warp;            // 0..4095
        const uint4* row = (const uint4*)(edges + (size_t)rowId * NN);
        unsigned myword = 0u;
        #pragma unroll
        for (int h = 0; h < 2; ++h) {
            uint4 v[4];
            #pragma unroll
            for (int j = 0; j < 4; ++j) v[j] = row[(h * 4 + j) * 32 + lane];
            #pragma unroll
            for (int j = 0; j < 4; ++j) {
                const int i = h * 4 + j;
                unsigned nib = (unsigned)(v[j].x != 0)
                             | ((unsigned)(v[j].y != 0) << 1)
                             | ((unsigned)(v[j].z != 0) << 2)
                             | ((unsigned)(v[j].w != 0) << 3);
                unsigned val = nib << ((lane & 7) * 4);
                val |= __shfl_xor_sync(FULL, val, 1);
                val |= __shfl_xor_sync(FULL, val, 2);
                val |= __shfl_xor_sync(FULL, val, 4);
                unsigned w = __shfl_sync(FULL, val, (lane & 3) << 3);
                if ((lane >> 2) == i) myword = w;
            }
        }
        g_bits[rowId * WPR + lane] = myword;                // coalesced

        if (blockIdx.x < 16) {
            // group maxes: warp task idx = b*32+g in [0,128)
            const int idx = blockIdx.x * 8 + warp;
            const float* f = feat + (size_t)idx * 32 * DD + lane;
            float m0 = f[0], m1 = f[DD], m2 = f[2 * DD], m3 = f[3 * DD];
            #pragma unroll
            for (int j = 4; j < 32; j += 4) {
                m0 = fmaxf(m0, f[j * DD]);
                m1 = fmaxf(m1, f[(j + 1) * DD]);
                m2 = fmaxf(m2, f[(j + 2) * DD]);
                m3 = fmaxf(m3, f[(j + 3) * DD]);
            }
            g_gm[idx * DD + lane] = fmaxf(fmaxf(m0, m1), fmaxf(m2, m3));
        }
    }

    // ===================== Device-wide barrier =====================
    __syncthreads();
    if (tid == 0) {
        __threadfence();                                    // release
        const unsigned t = atomicAdd(&g_arrive, 1u);
        const unsigned target = (t / NB + 1u) * NB;         // epoch end
        while (*(volatile unsigned*)&g_arrive < target) { } // spin
        __threadfence();                                    // acquire
    }
    __syncthreads();

    // ===================== Phase 2: pool =====================
    const int b = blockIdx.x >> 7;                 // batch
    const int i = (blockIdx.x & 127) * 8 + warp;   // output row in batch

    const unsigned* __restrict__ bb = g_bits + (size_t)b * NN * WPR;
    const float*    __restrict__ gm = g_gm + b * 32 * DD;
    const float*    __restrict__ fb = feat + (size_t)b * NN * DD;

    // One L2 epoch: rw + rows 0..31 stage + (warp0) gm reduction.
    const unsigned rw = bb[i * WPR + lane];                 // row i of E
    ((uint4*)sbits)[tid] = ((const uint4*)bb)[tid];         // rows 0..31
    if (warp == 0) {
        float m0 = gm[lane],      m1 = gm[32 + lane];
        float m2 = gm[64 + lane], m3 = gm[96 + lane];
        #pragma unroll
        for (int g = 4; g < 32; g += 4) {
            m0 = fmaxf(m0, gm[(g    ) * 32 + lane]);
            m1 = fmaxf(m1, gm[(g + 1) * 32 + lane]);
            m2 = fmaxf(m2, gm[(g + 2) * 32 + lane]);
            m3 = fmaxf(m3, gm[(g + 3) * 32 + lane]);
        }
        sbmax[lane] = fmaxf(fmaxf(m0, m1), fmaxf(m2, m3));
    }
    __syncthreads();

    // --- round 0 (word 0) from smem ---
    unsigned acc;
    bool sat;
    {
        const unsigned m = __shfl_sync(FULL, rw, 0);        // warp-uniform
        unsigned v0 = 0u, v1 = 0u, v2 = 0u, v3 = 0u;
        #pragma unroll
        for (int t = 0; t < 32; t += 4) {
            v0 |= sbits[((t    ) << 5) + lane] & (unsigned)((int)(m << (31 - t    )) >> 31);
            v1 |= sbits[((t + 1) << 5) + lane] & (unsigned)((int)(m << (31 - t - 1)) >> 31);
            v2 |= sbits[((t + 2) << 5) + lane] & (unsigned)((int)(m << (31 - t - 2)) >> 31);
            v3 |= sbits[((t + 3) << 5) + lane] & (unsigned)((int)(m << (31 - t - 3)) >> 31);
        }
        acc = (v0 | v1) | (v2 | v3);
        sat = __all_sync(FULL, acc == FULL);
    }

    if (sat) {
        out[((size_t)b * NN + i) * DD + lane] = sbmax[lane];
        return;
    }

    // --- rare rounds w>=1 from global (exact) ---
    #pragma unroll 1
    for (int w = 1; w < 32 && !sat; ++w) {
        const unsigned m = __shfl_sync(FULL, rw, w);
        if (!m) continue;
        const unsigned* __restrict__ gp = bb + ((size_t)w << 10) + lane;
        unsigned v0 = 0u, v1 = 0u, v2 = 0u, v3 = 0u;
        #pragma unroll
        for (int t = 0; t < 32; t += 4) {
            v0 |= gp[(t    ) << 5] & (unsigned)((int)(m << (31 - t    )) >> 31);
            v1 |= gp[(t + 1) << 5] & (unsigned)((int)(m << (31 - t - 1)) >> 31);
            v2 |= gp[(t + 2) << 5] & (unsigned)((int)(m << (31 - t - 2)) >> 31);
            v3 |= gp[(t + 3) << 5] & (unsigned)((int)(m << (31 - t - 3)) >> 31);
        }
        acc |= (v0 | v1) | (v2 | v3);
        sat = __all_sync(FULL, acc == FULL);
    }

    float best;
    if (sat) {
        best = sbmax[lane];
    } else {
        best = -INFINITY;
        #pragma unroll 1
        for (int g = 0; g < 32; ++g) {
            const unsigned mg = __shfl_sync(FULL, acc, g);   // uniform
            const float gmv = gm[(g << 5) + lane];           // L2
            float v;
            if (mg == FULL) {
                v = gmv;                        // whole group visible
            } else if (mg == 0u) {
                v = gmv + NEG_INF;              // whole group masked (exact)
            } else {
                v = -INFINITY;                  // mixed group: per-element
                for (int jj = 0; jj < 32; ++jj) {
                    float fv = fb[(size_t)((g << 5) + jj) * DD + lane];
                    v = fmaxf(v, fv + (((mg >> jj) & 1u) ? 0.0f : NEG_INF));
                }
            }
            best = fmaxf(best, v);
        }
    }
    out[((size_t)b * NN + i) * DD + lane] = best;   // coalesced 128B/warp
}

// ---------------------------------------------------------------------------
extern "C" void kernel_launch(void* const* d_in, const int* in_sizes, int n_in,
                              void* d_out, int out_size) {
    const float* feat;
    const int*   edges;
    if (in_sizes[0] == BATCH * NN * DD) {
        feat  = (const float*)d_in[0];
        edges = (const int*)d_in[1];
    } else {
        feat  = (const float*)d_in[1];
        edges = (const int*)d_in[0];
    }

    fused_kernel<<<NB, 256>>>(edges, feat, (float*)d_out);

    (void)n_in; (void)out_size;
}